// round 17
// baseline (speedup 1.0000x reference)
#include <cuda_runtime.h>

// SNN recurrence: B=1024, T=1024, H=32, I=2. One warp/batch, lane = unit.
// 2 warps/SMSP (128 blocks x 256 threads). Bit-exact reference-order ops
// (rel_err = 0.0 in every passing round), software-pipelined across bodies:
//   body k: consume u_k; compute u_{k+1} from x_{k+1}; soma V_{k-1}; group v_k;
//           preds p=s_k, q=S_{k-1} set at body end, consumed next body.
// R16: (a) intra-body interleave — v-chain / V-chain / u-term ops alternate so
// every dependent pair is >=3 instrs apart; (b) ld.shared.v4 loads TWO steps'
// x per instruction (2-set A/B alternation, load->use distance 1-2 bodies).

#define TT 1024

// body k: LDT loads x_{k+2},x_{k+3}; X0,X1 = x_{k+1}; UD = u_{k+1}; US = u_k
#define BDY(LDT, X0, X1, UD, US, AC) \
  LDT \
  "mul.rn.f32 t0, " X0 ", %10;\n\t"            /* u: x0*w0            */ \
  "mul.rn.f32 t1, " X1 ", %11;\n\t"            /* u: x1*w1            */ \
  "mul.rn.f32 %0, %0, %13;\n\t"                /* v = ag*v            */ \
  "mul.rn.f32 %1, %1, %14;\n\t"                /* V = as*V            */ \
  "add.rn.f32 t0, t0, t1;\n\t"                 /* u: gi               */ \
  "add.rn.f32 %0, %0, " US ";\n\t"             /* v += u_k            */ \
  "@p add.rn.f32 %1, %1, %15;\n\t"             /* V += bs (s_{k-1})   */ \
  AC                                           /* acc += S_{k-2}      */ \
  "mul.rn.f32 " UD ", %12, t0;\n\t"            /* u_{k+1} = bg*gi     */ \
  "@p add.rn.f32 %0, %0, 0fBF800000;\n\t"      /* v -= 1  (s_{k-1})   */ \
  "@q add.rn.f32 %1, %1, 0fBF800000;\n\t"      /* V -= 1  (S_{k-2})   */ \
  "setp.gt.f32 p, %0, 0f3F800000;\n\t"         /* p = s_k             */ \
  "setp.gt.f32 q, %1, 0f3F800000;\n\t"         /* q = S_{k-1}         */

#define LDA(OFF) "ld.shared.v4.f32 {a0,a1,a2,a3}, [%8+" OFF "];\n\t"
#define LDB(OFF) "ld.shared.v4.f32 {b0,b1,b2,b3}, [%8+" OFF "];\n\t"

// pair m even: load set A, read prev set B;  pair m odd: load B, read A
#define PA(OFF, AC) BDY(LDA(OFF), "b2", "b3", "ub", "ua", AC) \
                    BDY(""      , "a0", "a1", "ua", "ub", AC)
#define PB(OFF, AC) BDY(LDB(OFF), "a2", "a3", "ub", "ua", AC) \
                    BDY(""      , "b0", "b1", "ua", "ub", AC)

#define ACCQ "@q add.s32 %3, %3, 1;\n\t"

#define CHUNK(A0, A, TAIL) \
  "{\n\t" \
  ".reg .f32 a0,a1,a2,a3,b0,b1,b2,b3,t0,t1,ua,ub;\n\t" \
  ".reg .pred p,q;\n\t" \
  "mov.f32 ua, %2;\n\t" \
  "mov.f32 b2, %6;\n\t" \
  "mov.f32 b3, %7;\n\t" \
  "setp.gt.f32 p, %4, 0f3F000000;\n\t" \
  "setp.gt.f32 q, %5, 0f3F000000;\n\t" \
  PA("16", A0)  PB("32", A)   PA("48", A)   PB("64", A) \
  PA("80", A)   PB("96", A)   PA("112", A)  PB("128", A) \
  PA("144", A)  PB("160", A)  PA("176", A)  PB("192", A) \
  PA("208", A)  PB("224", A)  PA("240", A) \
  BDY("ld.shared.v4.f32 {b0,b1,b2,b3}, [%9];\n\t", "a2", "a3", "ub", "ua", A) \
  BDY("", "b0", "b1", "ua", "ub", A) \
  TAIL \
  "selp.f32 %4, 0f3F800000, 0f00000000, p;\n\t" \
  "selp.f32 %5, 0f3F800000, 0f00000000, q;\n\t" \
  "mov.f32 %2, ua;\n\t" \
  "mov.f32 %6, b2;\n\t" \
  "mov.f32 %7, b3;\n\t" \
  "}\n\t"

#define CHUNK_OPS \
  : "+f"(v), "+f"(V), "+f"(uc), "+r"(acc), "+f"(sF), "+f"(SF), "+f"(xc0), "+f"(xc1) \
  : "r"(cur), "r"(nxt), "f"(w0), "f"(w1), "f"(bg), "f"(ag), "f"(as), "f"(bs) \
  : "memory"

__global__ __launch_bounds__(256, 1)
void snn_kernel(const float* __restrict__ x,
                const float* __restrict__ Wg,     // [32,2]
                const float* __restrict__ tau_g,  // [32]
                const float* __restrict__ tau_s,  // [32]
                const float* __restrict__ Wout,   // [32]
                const float* __restrict__ bout,   // [1]
                float* __restrict__ out)          // [1024]
{
    const int lane = threadIdx.x & 31;
    const int wib  = threadIdx.x >> 5;
    const int b    = blockIdx.x * 8 + wib;

    __shared__ float4 sbuf[8][2][16];   // 16B-aligned: 2 steps per float4

    const float w0 = Wg[2 * lane];
    const float w1 = Wg[2 * lane + 1];
    const float ag = 1.0f / (1.0f + expf(-tau_g[lane]));
    const float bg = 1.0f - ag;
    const float as = 1.0f / (1.0f + expf(-tau_s[lane]));
    const float bs = 1.0f - as;

    const float2* xp = reinterpret_cast<const float2*>(x) + (size_t)b * TT;

    // Pipelined carries: uc = u_0, xc = x_1, spikes = 0
    float2 h0 = xp[0];
    float2 h1 = xp[1];
    float uc  = __fmul_rn(bg, __fadd_rn(__fmul_rn(h0.x, w0), __fmul_rn(h0.y, w1)));
    float xc0 = h1.x, xc1 = h1.y;
    float v = 0.0f, V = 0.0f, sF = 0.0f, SF = 0.0f;
    int acc = 0;

    // Prime both buffers: chunk 0 -> buf0, chunk 1 -> buf1
    reinterpret_cast<float2*>(&sbuf[wib][0][0])[lane] = xp[lane];
    reinterpret_cast<float2*>(&sbuf[wib][1][0])[lane] = xp[32 + lane];
    __syncwarp();

    const unsigned b0a = (unsigned)__cvta_generic_to_shared(&sbuf[wib][0][0]);
    const unsigned b1a = (unsigned)__cvta_generic_to_shared(&sbuf[wib][1][0]);

    #pragma unroll 1
    for (int c = 0; c < 32; ++c) {
        const unsigned cur = (c & 1) ? b1a : b0a;
        const unsigned nxt = (c & 1) ? b0a : b1a;
        float2 nd;
        if (c + 2 < 32) nd = xp[(c + 2) * 32 + lane];   // GMEM prefetch

        if (c < 24) {
            asm volatile(CHUNK("", "", "") CHUNK_OPS);
        } else if (c == 24) {
            asm volatile(CHUNK("", ACCQ, "") CHUNK_OPS);      // skip S_766,S_767
        } else if (c < 31) {
            asm volatile(CHUNK(ACCQ, ACCQ, "") CHUNK_OPS);
        } else {
            asm volatile(CHUNK(ACCQ, ACCQ, ACCQ) CHUNK_OPS);  // tail adds S_1022
        }

        if (c + 2 < 32) {
            reinterpret_cast<float2*>(&sbuf[wib][c & 1][0])[lane] = nd;
        }
        __syncwarp();
    }

    // Epilogue: finish soma step 1023 (body k computes V_{k-1}; last = V_1022).
    // V_1023 = as*V_1022 + bs*s_1023 - S_1022, exactly the reference sequence.
    {
        float m = __fmul_rn(bs, sF);                     // s_1023 in {0,1}
        float V1023 = __fsub_rn(__fadd_rn(__fmul_rn(as, V), m), SF);
        if (V1023 > 1.0f) acc += 1;                      // S_1023
    }

    // out[b] = sum_h acc_h * Wout[h] + bout  (identical reduction tree)
    float val = __fmul_rn((float)acc, Wout[lane]);
    #pragma unroll
    for (int off = 16; off; off >>= 1)
        val += __shfl_xor_sync(0xffffffffu, val, off);
    if (lane == 0) out[b] = val + bout[0];
}

extern "C" void kernel_launch(void* const* d_in, const int* in_sizes, int n_in,
                              void* d_out, int out_size) {
    const float* x    = (const float*)d_in[0];
    const float* Wg   = (const float*)d_in[1];
    const float* taug = (const float*)d_in[2];
    const float* taus = (const float*)d_in[3];
    const float* Wout = (const float*)d_in[4];
    const float* bout = (const float*)d_in[5];
    float* out = (float*)d_out;

    snn_kernel<<<128, 256>>>(x, Wg, taug, taus, Wout, bout, out);
}